// round 3
// baseline (speedup 1.0000x reference)
#include <cuda_runtime.h>
#include <cstdint>

// Problem constants
#define BATCH 16384
#define TT    10
#define II    184
#define HH    128

// Derived
#define K1 (II + HH)      // 312
#define K2 (256 + HH)     // 384

// ---------------------------------------------------------------------------
// Scratch (device globals; no allocation allowed)
// ---------------------------------------------------------------------------
__device__ float g_WT1[2 * K1 * 512];     // [dir][k][gate]  (gate = g*128 + j)
__device__ float g_B1 [2 * 512];
__device__ float g_WT2[2 * K2 * 512];
__device__ float g_B2 [2 * 512];
__device__ float g_O1 [BATCH * TT * 256]; // layer1 output (fwd|bwd concat)
__device__ float g_O2 [BATCH * TT * 256]; // layer2 output
__device__ float g_FC1T[512 * 64];        // fc1_w transposed: [k][j]

// ---------------------------------------------------------------------------
// f32x2 packed-math helpers (FFMA2 path, sm_100+)
// ---------------------------------------------------------------------------
typedef unsigned long long ull;

__device__ __forceinline__ ull pack2(float lo, float hi) {
    ull r;
    asm("mov.b64 %0, {%1, %2};" : "=l"(r) : "f"(lo), "f"(hi));
    return r;
}
__device__ __forceinline__ ull fma2(ull a, ull b, ull c) {
    ull d;
    asm("fma.rn.f32x2 %0, %1, %2, %3;" : "=l"(d) : "l"(a), "l"(b), "l"(c));
    return d;
}
__device__ __forceinline__ float2 unpack2(ull v) {
    float2 f;
    asm("mov.b64 {%0, %1}, %2;" : "=f"(f.x), "=f"(f.y) : "l"(v));
    return f;
}

__device__ __forceinline__ float sigf(float x) {
    return 1.0f / (1.0f + __expf(-x));
}
__device__ __forceinline__ float tanh_fast(float x) {
    // tanh(x) = 2*sigmoid(2x) - 1 ; expf-based, ~1e-7 rel err
    return 2.0f / (1.0f + __expf(-2.0f * x)) - 1.0f;
}

// ---------------------------------------------------------------------------
// Prep: build concatenated transposed weights WT[dir][k][512] and bias sums
// ---------------------------------------------------------------------------
__global__ void prep_layer(const float* __restrict__ wih,
                           const float* __restrict__ whh,
                           const float* __restrict__ bih,
                           const float* __restrict__ bhh,
                           int IN, float* __restrict__ wt,
                           float* __restrict__ bias)
{
    const int KT = IN + HH;
    const int total = KT * 512;
    for (int idx = blockIdx.x * blockDim.x + threadIdx.x; idx < total;
         idx += gridDim.x * blockDim.x) {
        int k = idx >> 9;          // /512
        int g = idx & 511;
        wt[idx] = (k < IN) ? wih[g * IN + k] : whh[g * HH + (k - IN)];
    }
    int gidx = blockIdx.x * blockDim.x + threadIdx.x;
    if (gidx < 512) bias[gidx] = bih[gidx] + bhh[gidx];
}

__global__ void prep_fc(const float* __restrict__ fc1w, float* __restrict__ fct)
{
    int idx = blockIdx.x * blockDim.x + threadIdx.x;
    if (idx < 512 * 64) {
        int j = idx / 512;
        int k = idx % 512;
        fct[k * 64 + j] = fc1w[idx];
    }
}

// ---------------------------------------------------------------------------
// Fused LSTM layer kernel.
//  One CTA = 64 batch rows x one direction. 512 threads.
//  Per step: GEMM (64 x KTOT) @ (KTOT x 512) with [x_t ; h] in SMEM,
//  weights streamed from L2 (fully cached), c-state in registers.
//  Thread tile: 4 batch x 4 hidden-j x 4 gates, j paired for fma.rn.f32x2.
// ---------------------------------------------------------------------------
template<int IN, int KTOT>
__global__ __launch_bounds__(512, 1)
void lstm_kernel(const float* __restrict__ inp,   // [B][T][IN]
                 const float* __restrict__ wt,    // [2][KTOT][512]
                 const float* __restrict__ bias,  // [2][512]
                 float* __restrict__ outp)        // [B][T][256]
{
    extern __shared__ float in_s[];   // [64][KTOT]  layout b-major
    const int dir = blockIdx.y;
    const int b0  = blockIdx.x * 64;
    const float* W  = wt + (size_t)dir * KTOT * 512;
    const float* Bv = bias + dir * 512;

    const int tid = threadIdx.x;
    const int jq  = tid & 31;    // hidden quartet: j = jq*4 .. jq*4+3
    const int bq  = tid >> 5;    // batch quartet (warp id): b = bq*4 .. bq*4+3

    // zero h region of SMEM
    for (int idx = tid; idx < 64 * HH; idx += 512) {
        int b = idx >> 7;
        int k = idx & 127;
        in_s[b * KTOT + IN + k] = 0.0f;
    }

    float cst[4][4];   // [j within quartet][batch within quartet]
#pragma unroll
    for (int a = 0; a < 4; a++)
#pragma unroll
        for (int b = 0; b < 4; b++) cst[a][b] = 0.0f;

    const float* xs[4];
#pragma unroll
    for (int bb = 0; bb < 4; bb++) xs[bb] = in_s + (bq * 4 + bb) * KTOT;

    for (int step = 0; step < TT; ++step) {
        const int t = dir ? (TT - 1 - step) : step;

        // stage x_t for this tile (coalesced)
        for (int idx = tid; idx < 64 * IN; idx += 512) {
            int b = idx / IN;
            int k = idx - b * IN;
            in_s[b * KTOT + k] = inp[((size_t)(b0 + b) * TT + t) * IN + k];
        }
        __syncthreads();

        // accumulators: [gate][j-pair][batch], packed f32x2 over j
        ull acc[4][2][4];
#pragma unroll
        for (int g = 0; g < 4; g++) {
            float4 bv = *reinterpret_cast<const float4*>(Bv + g * 128 + jq * 4);
            ull p0 = pack2(bv.x, bv.y);
            ull p1 = pack2(bv.z, bv.w);
#pragma unroll
            for (int bb = 0; bb < 4; bb++) { acc[g][0][bb] = p0; acc[g][1][bb] = p1; }
        }

        const float* Wp = W + jq * 4;
#pragma unroll 2
        for (int k = 0; k < KTOT; ++k) {
            ulonglong2 wv[4];
#pragma unroll
            for (int g = 0; g < 4; g++)
                wv[g] = *reinterpret_cast<const ulonglong2*>(Wp + g * 128);

            ull xp[4];
#pragma unroll
            for (int bb = 0; bb < 4; bb++) {
                float xv = xs[bb][k];
                xp[bb] = pack2(xv, xv);
            }
#pragma unroll
            for (int g = 0; g < 4; g++) {
#pragma unroll
                for (int bb = 0; bb < 4; bb++) {
                    acc[g][0][bb] = fma2(wv[g].x, xp[bb], acc[g][0][bb]);
                    acc[g][1][bb] = fma2(wv[g].y, xp[bb], acc[g][1][bb]);
                }
            }
            Wp += 512;
        }

        __syncthreads();   // everyone done reading in_s before h rewrite

        // activations + state update + h writeback
#pragma unroll
        for (int jp = 0; jp < 2; jp++) {
#pragma unroll
            for (int bb = 0; bb < 4; bb++) {
                float2 iv2 = unpack2(acc[0][jp][bb]);
                float2 fv2 = unpack2(acc[1][jp][bb]);
                float2 gv2 = unpack2(acc[2][jp][bb]);
                float2 ov2 = unpack2(acc[3][jp][bb]);
#pragma unroll
                for (int half = 0; half < 2; half++) {
                    float ig = half ? iv2.y : iv2.x;
                    float fg = half ? fv2.y : fv2.x;
                    float gg = half ? gv2.y : gv2.x;
                    float og = half ? ov2.y : ov2.x;
                    int jidx = jp * 2 + half;

                    float i_ = sigf(ig);
                    float f_ = sigf(fg);
                    float g_ = tanh_fast(gg);
                    float o_ = sigf(og);
                    float cc = f_ * cst[jidx][bb] + i_ * g_;
                    cst[jidx][bb] = cc;
                    float hv = o_ * tanh_fast(cc);

                    int j = jq * 4 + jidx;
                    int b = b0 + bq * 4 + bb;
                    in_s[(bq * 4 + bb) * KTOT + IN + j] = hv;
                    outp[((size_t)b * TT + t) * 256 + dir * HH + j] = hv;
                }
            }
        }
        // next iteration's __syncthreads (after x load) publishes new h
    }
}

// ---------------------------------------------------------------------------
// Head: temporal max-pool (2 windows of 5) + fc1(512->64, relu) + fc2(64->1)
// Block: 256 threads = 4 batch rows, 64 threads per row.
// pooled flat index = channel*2 + window  (matches transpose(0,2,1).reshape)
// ---------------------------------------------------------------------------
__global__ void head_kernel(const float* __restrict__ O2,
                            const float* __restrict__ fc1t,  // [k][64]
                            const float* __restrict__ fc1b,
                            const float* __restrict__ fc2w,
                            const float* __restrict__ fc2b,
                            float* __restrict__ out)
{
    __shared__ float pooled[4][512];
    __shared__ float red[4][2];

    const int tid = threadIdx.x;
    const int r   = tid >> 6;          // row within block (0..3)
    const int l   = tid & 63;          // lane within row
    const int b   = blockIdx.x * 4 + r;

#pragma unroll
    for (int ci = 0; ci < 4; ci++) {
        int c = l + ci * 64;           // channel 0..255
#pragma unroll
        for (int p = 0; p < 2; p++) {
            float m = -3.4e38f;
#pragma unroll
            for (int w = 0; w < 5; w++) {
                float v = O2[((size_t)b * TT + p * 5 + w) * 256 + c];
                m = fmaxf(m, v);
            }
            pooled[r][c * 2 + p] = m;
        }
    }
    __syncthreads();

    // fc1 output j = l  (64 outputs), then fc2 dot via reduction
    float s = fc1b[l];
    for (int k = 0; k < 512; k++)
        s += pooled[r][k] * fc1t[k * 64 + l];
    float v = fmaxf(s, 0.0f) * fc2w[l];

#pragma unroll
    for (int off = 16; off > 0; off >>= 1)
        v += __shfl_down_sync(0xffffffffu, v, off);
    if ((tid & 31) == 0) red[r][(tid >> 5) & 1] = v;
    __syncthreads();
    if (l == 0) out[b] = red[r][0] + red[r][1] + fc2b[0];
}

// ---------------------------------------------------------------------------
// Launch
// ---------------------------------------------------------------------------
extern "C" void kernel_launch(void* const* d_in, const int* in_sizes, int n_in,
                              void* d_out, int out_size)
{
    (void)in_sizes; (void)n_in; (void)out_size;
    const float* x       = (const float*)d_in[0];
    const float* w_ih1_f = (const float*)d_in[1];
    const float* w_hh1_f = (const float*)d_in[2];
    const float* b_ih1_f = (const float*)d_in[3];
    const float* b_hh1_f = (const float*)d_in[4];
    const float* w_ih1_b = (const float*)d_in[5];
    const float* w_hh1_b = (const float*)d_in[6];
    const float* b_ih1_b = (const float*)d_in[7];
    const float* b_hh1_b = (const float*)d_in[8];
    const float* w_ih2_f = (const float*)d_in[9];
    const float* w_hh2_f = (const float*)d_in[10];
    const float* b_ih2_f = (const float*)d_in[11];
    const float* b_hh2_f = (const float*)d_in[12];
    const float* w_ih2_b = (const float*)d_in[13];
    const float* w_hh2_b = (const float*)d_in[14];
    const float* b_ih2_b = (const float*)d_in[15];
    const float* b_hh2_b = (const float*)d_in[16];
    const float* fc1_w   = (const float*)d_in[17];
    const float* fc1_b   = (const float*)d_in[18];
    const float* fc2_w   = (const float*)d_in[19];
    const float* fc2_b   = (const float*)d_in[20];
    float* out = (float*)d_out;

    float *WT1, *B1, *WT2, *B2, *O1, *O2, *FC1T;
    cudaGetSymbolAddress((void**)&WT1,  g_WT1);
    cudaGetSymbolAddress((void**)&B1,   g_B1);
    cudaGetSymbolAddress((void**)&WT2,  g_WT2);
    cudaGetSymbolAddress((void**)&B2,   g_B2);
    cudaGetSymbolAddress((void**)&O1,   g_O1);
    cudaGetSymbolAddress((void**)&O2,   g_O2);
    cudaGetSymbolAddress((void**)&FC1T, g_FC1T);

    // weight prep (tiny)
    prep_layer<<<192, 256>>>(w_ih1_f, w_hh1_f, b_ih1_f, b_hh1_f, II, WT1,            B1);
    prep_layer<<<192, 256>>>(w_ih1_b, w_hh1_b, b_ih1_b, b_hh1_b, II, WT1 + K1 * 512, B1 + 512);
    prep_layer<<<192, 256>>>(w_ih2_f, w_hh2_f, b_ih2_f, b_hh2_f, 256, WT2,            B2);
    prep_layer<<<192, 256>>>(w_ih2_b, w_hh2_b, b_ih2_b, b_hh2_b, 256, WT2 + K2 * 512, B2 + 512);
    prep_fc<<<64, 512>>>(fc1_w, FC1T);

    const int smem1 = 64 * K1 * (int)sizeof(float);   // 79872
    const int smem2 = 64 * K2 * (int)sizeof(float);   // 98304
    cudaFuncSetAttribute(lstm_kernel<II, K1>,
                         cudaFuncAttributeMaxDynamicSharedMemorySize, smem1);
    cudaFuncSetAttribute(lstm_kernel<256, K2>,
                         cudaFuncAttributeMaxDynamicSharedMemorySize, smem2);

    dim3 grid(BATCH / 64, 2);
    lstm_kernel<II, K1><<<grid, 512, smem1>>>(x,  WT1, B1, O1);
    lstm_kernel<256, K2><<<grid, 512, smem2>>>(O1, WT2, B2, O2);

    head_kernel<<<BATCH / 4, 256>>>(O2, FC1T, fc1_b, fc2_w, fc2_b, out);
}

// round 5
// speedup vs baseline: 2.2920x; 2.2920x over previous
#include <cuda_runtime.h>
#include <cstdint>

// Problem constants
#define BATCH 16384
#define TT    10
#define II    184
#define HH    128

// Derived
#define K1 (II + HH)      // 312
#define K2 (256 + HH)     // 384
#define CK 24             // k-chunk rows staged in SMEM (divides 312 and 384)

// ---------------------------------------------------------------------------
// Scratch (device globals; no allocation allowed)
// ---------------------------------------------------------------------------
__device__ float g_WT1[2 * K1 * 512];     // [dir][k][gate]  (gate = g*128 + j)
__device__ float g_B1 [2 * 512];
__device__ float g_WT2[2 * K2 * 512];
__device__ float g_B2 [2 * 512];
__device__ float g_O1 [BATCH * TT * 256]; // layer1 output (fwd|bwd concat)
__device__ float g_O2 [BATCH * TT * 256]; // layer2 output
__device__ float g_FC1T[512 * 64];        // fc1_w transposed: [k][j]

// ---------------------------------------------------------------------------
// f32x2 packed-math helpers (FFMA2 path, sm_100+)
// ---------------------------------------------------------------------------
typedef unsigned long long ull;

__device__ __forceinline__ ull pack2(float lo, float hi) {
    ull r;
    asm("mov.b64 %0, {%1, %2};" : "=l"(r) : "f"(lo), "f"(hi));
    return r;
}
__device__ __forceinline__ ull fma2(ull a, ull b, ull c) {
    ull d;
    asm("fma.rn.f32x2 %0, %1, %2, %3;" : "=l"(d) : "l"(a), "l"(b), "l"(c));
    return d;
}
__device__ __forceinline__ float2 unpack2(ull v) {
    float2 f;
    asm("mov.b64 {%0, %1}, %2;" : "=f"(f.x), "=f"(f.y) : "l"(v));
    return f;
}

__device__ __forceinline__ float sigf(float x) {
    return 1.0f / (1.0f + __expf(-x));
}
__device__ __forceinline__ float tanh_fast(float x) {
    return 2.0f / (1.0f + __expf(-2.0f * x)) - 1.0f;
}

// cp.async helpers
__device__ __forceinline__ void cp16(float* dst_smem, const float* src) {
    unsigned saddr = (unsigned)__cvta_generic_to_shared(dst_smem);
    asm volatile("cp.async.cg.shared.global [%0], [%1], 16;"
                 :: "r"(saddr), "l"(src));
}
__device__ __forceinline__ void cp_commit() {
    asm volatile("cp.async.commit_group;");
}
__device__ __forceinline__ void cp_wait0() {
    asm volatile("cp.async.wait_group 0;" ::: "memory");
}

// ---------------------------------------------------------------------------
// Fused prep (single launch): build WT[dir][k][512] for both layers,
// bias sums, and fc1 transpose.
// ---------------------------------------------------------------------------
__global__ void prep_all(const float* __restrict__ wih1f, const float* __restrict__ whh1f,
                         const float* __restrict__ bih1f, const float* __restrict__ bhh1f,
                         const float* __restrict__ wih1b, const float* __restrict__ whh1b,
                         const float* __restrict__ bih1b, const float* __restrict__ bhh1b,
                         const float* __restrict__ wih2f, const float* __restrict__ whh2f,
                         const float* __restrict__ bih2f, const float* __restrict__ bhh2f,
                         const float* __restrict__ wih2b, const float* __restrict__ whh2b,
                         const float* __restrict__ bih2b, const float* __restrict__ bhh2b,
                         const float* __restrict__ fc1w,
                         float* __restrict__ wt1, float* __restrict__ b1,
                         float* __restrict__ wt2, float* __restrict__ b2,
                         float* __restrict__ fct)
{
    const int stride = gridDim.x * blockDim.x;
    const int tid0 = blockIdx.x * blockDim.x + threadIdx.x;

    // layer1: 2 dirs, K1*512 each
    for (int idx = tid0; idx < 2 * K1 * 512; idx += stride) {
        int dir = idx / (K1 * 512);
        int r   = idx - dir * (K1 * 512);
        int k = r >> 9, g = r & 511;
        const float* wih = dir ? wih1b : wih1f;
        const float* whh = dir ? whh1b : whh1f;
        wt1[idx] = (k < II) ? wih[g * II + k] : whh[g * HH + (k - II)];
    }
    // layer2
    for (int idx = tid0; idx < 2 * K2 * 512; idx += stride) {
        int dir = idx / (K2 * 512);
        int r   = idx - dir * (K2 * 512);
        int k = r >> 9, g = r & 511;
        const float* wih = dir ? wih2b : wih2f;
        const float* whh = dir ? whh2b : whh2f;
        wt2[idx] = (k < 256) ? wih[g * 256 + k] : whh[g * HH + (k - 256)];
    }
    // biases
    for (int idx = tid0; idx < 512; idx += stride) {
        b1[idx]       = bih1f[idx] + bhh1f[idx];
        b1[idx + 512] = bih1b[idx] + bhh1b[idx];
        b2[idx]       = bih2f[idx] + bhh2f[idx];
        b2[idx + 512] = bih2b[idx] + bhh2b[idx];
    }
    // fc1 transpose
    for (int idx = tid0; idx < 512 * 64; idx += stride) {
        int j = idx / 512, k = idx % 512;
        fct[k * 64 + j] = fc1w[idx];
    }
}

// ---------------------------------------------------------------------------
// Fused LSTM layer kernel, SMEM-staged weights.
//  CTA = 64 batch x one direction, 512 threads.
//  SMEM: in_s [64][KTOT] ([x_t ; h]) + double-buffered weight chunk [2][CK][512].
//  Weights stream L2 -> SMEM once per CTA per step (cp.async, 1-deep pipeline).
//  Thread tile: 4 batch x 4 hidden-j x 4 gates, j paired for fma.rn.f32x2.
// ---------------------------------------------------------------------------
template<int IN, int KTOT>
__global__ __launch_bounds__(512, 1)
void lstm_kernel(const float* __restrict__ inp,   // [B][T][IN]
                 const float* __restrict__ wt,    // [2][KTOT][512]
                 const float* __restrict__ bias,  // [2][512]
                 float* __restrict__ outp)        // [B][T][256]
{
    constexpr int NC = KTOT / CK;                 // chunks per step
    extern __shared__ float smem[];
    float* in_s = smem;                           // [64][KTOT]
    float* wbuf = smem + 64 * KTOT;               // [2][CK][512]

    const int dir = blockIdx.y;
    const int b0  = blockIdx.x * 64;
    const float* W  = wt + (size_t)dir * KTOT * 512;
    const float* Bv = bias + dir * 512;

    const int tid = threadIdx.x;
    const int jq  = tid & 31;    // hidden quartet: j = jq*4 .. jq*4+3
    const int bq  = tid >> 5;    // batch quartet (warp id): b = bq*4 .. bq*4+3

    // zero h region of SMEM
    for (int idx = tid; idx < 64 * HH; idx += 512) {
        int b = idx >> 7;
        int k = idx & 127;
        in_s[b * KTOT + IN + k] = 0.0f;
    }
    __syncthreads();

    float cst[4][4];   // [j within quartet][batch within quartet]
#pragma unroll
    for (int a = 0; a < 4; a++)
#pragma unroll
        for (int b = 0; b < 4; b++) cst[a][b] = 0.0f;

    const float* xs = in_s + bq * 4 * KTOT;       // base for this thread's 4 rows

    for (int step = 0; step < TT; ++step) {
        const int t = dir ? (TT - 1 - step) : step;

        // stage x_t for this tile (coalesced; h region untouched)
        for (int idx = tid; idx < 64 * IN; idx += 512) {
            int b = idx / IN;
            int k = idx - b * IN;
            in_s[b * KTOT + k] = inp[((size_t)(b0 + b) * TT + t) * IN + k];
        }

        // prologue: load chunk 0 into buf 0 (buf0 free: prev step fully synced)
        {
            const float* src = W;                 // k rows [0, CK)
            float* dst = wbuf;
#pragma unroll
            for (int i = 0; i < CK * 512 / (512 * 4); i++)   // 6 x 16B per thread
                cp16(dst + (tid + i * 512) * 4, src + (tid + i * 512) * 4);
            cp_commit();
        }

        // accumulators: [gate][j-pair][batch], packed f32x2 over j
        ull acc[4][2][4];
#pragma unroll
        for (int g = 0; g < 4; g++) {
            float4 bv = *reinterpret_cast<const float4*>(Bv + g * 128 + jq * 4);
            ull p0 = pack2(bv.x, bv.y);
            ull p1 = pack2(bv.z, bv.w);
#pragma unroll
            for (int bb = 0; bb < 4; bb++) { acc[g][0][bb] = p0; acc[g][1][bb] = p1; }
        }

        for (int c = 0; c < NC; ++c) {
            cp_wait0();                 // chunk c landed
            __syncthreads();            // visible to all; prev chunk compute done

            if (c + 1 < NC) {           // prefetch chunk c+1 (overlaps compute c)
                const float* src = W + (size_t)(c + 1) * CK * 512;
                float* dst = wbuf + ((c + 1) & 1) * CK * 512;
#pragma unroll
                for (int i = 0; i < CK * 512 / (512 * 4); i++)
                    cp16(dst + (tid + i * 512) * 4, src + (tid + i * 512) * 4);
                cp_commit();
            }

            const float* wch = wbuf + (c & 1) * CK * 512 + jq * 4;
            const int kbase = c * CK;
#pragma unroll 2
            for (int kk = 0; kk < CK; ++kk) {
                ulonglong2 wv[4];
#pragma unroll
                for (int g = 0; g < 4; g++)
                    wv[g] = *reinterpret_cast<const ulonglong2*>(wch + kk * 512 + g * 128);

                const int k = kbase + kk;
                ull xp[4];
#pragma unroll
                for (int bb = 0; bb < 4; bb++) {
                    float xv = xs[bb * KTOT + k];
                    xp[bb] = pack2(xv, xv);
                }
#pragma unroll
                for (int g = 0; g < 4; g++) {
#pragma unroll
                    for (int bb = 0; bb < 4; bb++) {
                        acc[g][0][bb] = fma2(wv[g].x, xp[bb], acc[g][0][bb]);
                        acc[g][1][bb] = fma2(wv[g].y, xp[bb], acc[g][1][bb]);
                    }
                }
            }
        }

        __syncthreads();   // all reads of in_s done before h rewrite

        // activations + state update + h writeback
#pragma unroll
        for (int jp = 0; jp < 2; jp++) {
#pragma unroll
            for (int bb = 0; bb < 4; bb++) {
                float2 iv2 = unpack2(acc[0][jp][bb]);
                float2 fv2 = unpack2(acc[1][jp][bb]);
                float2 gv2 = unpack2(acc[2][jp][bb]);
                float2 ov2 = unpack2(acc[3][jp][bb]);
#pragma unroll
                for (int half = 0; half < 2; half++) {
                    float ig = half ? iv2.y : iv2.x;
                    float fg = half ? fv2.y : fv2.x;
                    float gg = half ? gv2.y : gv2.x;
                    float og = half ? ov2.y : ov2.x;
                    int jidx = jp * 2 + half;

                    float i_ = sigf(ig);
                    float f_ = sigf(fg);
                    float g_ = tanh_fast(gg);
                    float o_ = sigf(og);
                    float cc = f_ * cst[jidx][bb] + i_ * g_;
                    cst[jidx][bb] = cc;
                    float hv = o_ * tanh_fast(cc);

                    int j = jq * 4 + jidx;
                    int b = b0 + bq * 4 + bb;
                    in_s[(bq * 4 + bb) * KTOT + IN + j] = hv;
                    outp[((size_t)b * TT + t) * 256 + dir * HH + j] = hv;
                }
            }
        }
        __syncthreads();   // epilogue done before next step stages x / reuses buf0
    }
}

// ---------------------------------------------------------------------------
// Head: temporal max-pool (2 windows of 5) + fc1(512->64, relu) + fc2(64->1)
// ---------------------------------------------------------------------------
__global__ void head_kernel(const float* __restrict__ O2,
                            const float* __restrict__ fc1t,  // [k][64]
                            const float* __restrict__ fc1b,
                            const float* __restrict__ fc2w,
                            const float* __restrict__ fc2b,
                            float* __restrict__ out)
{
    __shared__ float pooled[4][512];
    __shared__ float red[4][2];

    const int tid = threadIdx.x;
    const int r   = tid >> 6;          // row within block (0..3)
    const int l   = tid & 63;          // lane within row
    const int b   = blockIdx.x * 4 + r;

#pragma unroll
    for (int ci = 0; ci < 4; ci++) {
        int c = l + ci * 64;           // channel 0..255
#pragma unroll
        for (int p = 0; p < 2; p++) {
            float m = -3.4e38f;
#pragma unroll
            for (int w = 0; w < 5; w++) {
                float v = O2[((size_t)b * TT + p * 5 + w) * 256 + c];
                m = fmaxf(m, v);
            }
            pooled[r][c * 2 + p] = m;
        }
    }
    __syncthreads();

    float s = fc1b[l];
    for (int k = 0; k < 512; k++)
        s += pooled[r][k] * fc1t[k * 64 + l];
    float v = fmaxf(s, 0.0f) * fc2w[l];

#pragma unroll
    for (int off = 16; off > 0; off >>= 1)
        v += __shfl_down_sync(0xffffffffu, v, off);
    if ((tid & 31) == 0) red[r][(tid >> 5) & 1] = v;
    __syncthreads();
    if (l == 0) out[b] = red[r][0] + red[r][1] + fc2b[0];
}

// ---------------------------------------------------------------------------
// Launch
// ---------------------------------------------------------------------------
extern "C" void kernel_launch(void* const* d_in, const int* in_sizes, int n_in,
                              void* d_out, int out_size)
{
    (void)in_sizes; (void)n_in; (void)out_size;
    const float* x       = (const float*)d_in[0];
    const float* fc1_b   = (const float*)d_in[18];
    const float* fc2_w   = (const float*)d_in[19];
    const float* fc2_b   = (const float*)d_in[20];
    float* out = (float*)d_out;

    float *WT1, *B1, *WT2, *B2, *O1, *O2, *FC1T;
    cudaGetSymbolAddress((void**)&WT1,  g_WT1);
    cudaGetSymbolAddress((void**)&B1,   g_B1);
    cudaGetSymbolAddress((void**)&WT2,  g_WT2);
    cudaGetSymbolAddress((void**)&B2,   g_B2);
    cudaGetSymbolAddress((void**)&O1,   g_O1);
    cudaGetSymbolAddress((void**)&O2,   g_O2);
    cudaGetSymbolAddress((void**)&FC1T, g_FC1T);

    // single fused prep launch (keeps ncu's -s window on the LSTM kernels)
    prep_all<<<296, 256>>>((const float*)d_in[1],  (const float*)d_in[2],
                           (const float*)d_in[3],  (const float*)d_in[4],
                           (const float*)d_in[5],  (const float*)d_in[6],
                           (const float*)d_in[7],  (const float*)d_in[8],
                           (const float*)d_in[9],  (const float*)d_in[10],
                           (const float*)d_in[11], (const float*)d_in[12],
                           (const float*)d_in[13], (const float*)d_in[14],
                           (const float*)d_in[15], (const float*)d_in[16],
                           (const float*)d_in[17],
                           WT1, B1, WT2, B2, FC1T);

    const int smem1 = (64 * K1 + 2 * CK * 512) * (int)sizeof(float);  // 178176
    const int smem2 = (64 * K2 + 2 * CK * 512) * (int)sizeof(float);  // 196608
    cudaFuncSetAttribute(lstm_kernel<II, K1>,
                         cudaFuncAttributeMaxDynamicSharedMemorySize, smem1);
    cudaFuncSetAttribute(lstm_kernel<256, K2>,
                         cudaFuncAttributeMaxDynamicSharedMemorySize, smem2);

    dim3 grid(BATCH / 64, 2);
    lstm_kernel<II, K1><<<grid, 512, smem1>>>(x,  WT1, B1, O1);
    lstm_kernel<256, K2><<<grid, 512, smem2>>>(O1, WT2, B2, O2);

    head_kernel<<<BATCH / 4, 256>>>(O2, FC1T, fc1_b, fc2_w, fc2_b, out);
}